// round 14
// baseline (speedup 1.0000x reference)
#include <cuda_runtime.h>
#include <cuda_fp16.h>
#include <mma.h>
#include <math.h>

using namespace nvcuda;

#define Bsz 128
#define Nn  512
#define Ff  64
#define Dd  64
#define Kk  20
#define BN  (Bsz*Nn)          // 65536
#define NELEM (BN*Dd)         // 4194304
#define AGRID 512             // attn: 4 blocks per batch
#define TGRID 512             // tail grid
#define PRE_BLOCKS 32         // 16 nodes per block (2 per warp)

// ---------------- device scratch (no allocations allowed) ----------------
__device__ __half2 d_gh2[NELEM/2];        // g in fp16, [row][64]
__device__ float d_agg[NELEM];            // agg fp32
__device__ float d_si[BN];
__device__ float d_sj[BN];
__device__ float d_eai[Nn];
__device__ float d_eaj[Nn];
__device__ int   d_topk[Nn*Kk];
__device__ float d_ps1[64*AGRID];         // channel-major BN1 partials
__device__ float d_pq1[64*AGRID];
__device__ float d_ps2[64*TGRID];         // channel-major BN2 partials
__device__ float d_pq2[64*TGRID];
__device__ float d_scale1[64], d_shift1[64], d_scale2[64], d_shift2[64];
__device__ unsigned g_bar;                // monotonic grid-barrier counter

__device__ __forceinline__ float warpSum(float v){
  #pragma unroll
  for(int o=16;o;o>>=1) v += __shfl_xor_sync(0xffffffffu, v, o);
  return v;
}

// ==== fused work kernel: blocks 0-31 -> pre(topk), blocks 32-543 -> gemm ====
#define GS_XH 0
#define GS_WH 18432
#define GS_CS 27648
#define WORK_SMEM (27648 + 128*68*4)   // 62464 bytes (gemm layout; pre fits inside)

// pre: 8 warps, 2 nodes each; 4 chunks of 128 e_norm rows; interleaved top-K.
__device__ void pre_body(char* gsm, const float* __restrict__ embed,
                         const float* __restrict__ aemi,
                         const float* __restrict__ aemj){
  float* tile  = reinterpret_cast<float*>(gsm);            // 128*68
  float* srows = tile + 128*68;                            // 16*68
  float* invn  = srows + 16*68;                            // 128
  int t = threadIdx.x, w = t>>5, lane = t&31;
  int node0 = blockIdx.x*16 + w*2;

  // load this block's 16 source rows (256 float4, one per thread)
  {
    int r = t >> 4, c4 = t & 15;
    float4 v = reinterpret_cast<const float4*>(embed)[(blockIdx.x*16 + r)*16 + c4];
    *reinterpret_cast<float4*>(&srows[r*68 + c4*4]) = v;
  }
  __syncthreads();
  // normalize own 2 rows + eai/eaj
  #pragma unroll
  for(int nn=0; nn<2; nn++){
    int r = w*2 + nn;
    float v0 = srows[r*68+lane], v1 = srows[r*68+32+lane];
    float ss = warpSum(v0*v0 + v1*v1);
    float inv = 1.0f/(sqrtf(ss)+1e-12f);
    float si = warpSum(v0*aemi[lane] + v1*aemi[lane+32]);
    float sj = warpSum(v0*aemj[lane] + v1*aemj[lane+32]);
    if(lane==0){ d_eai[node0+nn]=si; d_eaj[node0+nn]=sj; }
    srows[r*68+lane]    = v0*inv;
    srows[r*68+32+lane] = v1*inv;
  }

  float sims0[16], sims1[16];
  #pragma unroll
  for(int chunk=0; chunk<4; chunk++){
    __syncthreads();
    // load 128-row chunk (2048 float4, 8/thread)
    #pragma unroll
    for(int q=0; q<8; q++){
      int idx = t + q*256;
      int r = idx >> 4, c4 = idx & 15;
      float4 v = reinterpret_cast<const float4*>(embed)[(chunk*128 + r)*16 + c4];
      *reinterpret_cast<float4*>(&tile[r*68 + c4*4]) = v;
    }
    __syncthreads();
    if(t < 128){
      const float* rr = &tile[t*68];
      float ss = 0.f;
      #pragma unroll
      for(int q=0; q<16; q++){
        float4 v = *reinterpret_cast<const float4*>(&rr[q*4]);
        ss += v.x*v.x + v.y*v.y + v.z*v.z + v.w*v.w;
      }
      invn[t] = 1.0f/(sqrtf(ss)+1e-12f);
    }
    __syncthreads();
    #pragma unroll
    for(int q=0; q<8; q++){
      int idx = t + q*256;
      int r = idx >> 4;
      float inv = invn[r];
      float4* p = reinterpret_cast<float4*>(&tile[r*68 + (idx&15)*4]);
      float4 v = *p;
      v.x*=inv; v.y*=inv; v.z*=inv; v.w*=inv;
      *p = v;
    }
    __syncthreads();
    const float* s0 = &srows[(w*2+0)*68];
    const float* s1 = &srows[(w*2+1)*68];
    float a0[4] = {0.f,0.f,0.f,0.f};
    float a1[4] = {0.f,0.f,0.f,0.f};
    #pragma unroll
    for(int kk=0; kk<64; kk+=4){
      float4 sA = *reinterpret_cast<const float4*>(&s0[kk]);
      float4 sB = *reinterpret_cast<const float4*>(&s1[kk]);
      #pragma unroll
      for(int qq=0; qq<4; qq++){
        float4 e = *reinterpret_cast<const float4*>(&tile[(qq*32+lane)*68+kk]);
        a0[qq] += sA.x*e.x + sA.y*e.y + sA.z*e.z + sA.w*e.w;
        a1[qq] += sB.x*e.x + sB.y*e.y + sB.z*e.z + sB.w*e.w;
      }
    }
    #pragma unroll
    for(int qq=0; qq<4; qq++){
      sims0[chunk*4+qq] = a0[qq];   // j = chunk*128 + qq*32 + lane
      sims1[chunk*4+qq] = a1[qq];
    }
  }

  // interleaved top-K selection for both nodes (independent chains pipeline)
  for(int sel=0; sel<Kk; sel++){
    float bv0 = -INFINITY, bv1 = -INFINITY;
    int bj0 = 0x3fffffff, bj1 = 0x3fffffff;
    #pragma unroll
    for(int s=0; s<16; s++){
      int j = (s>>2)*128 + (s&3)*32 + lane;
      float v0 = sims0[s], v1 = sims1[s];
      if(v0 > bv0 || (v0 == bv0 && j < bj0)){ bv0 = v0; bj0 = j; }
      if(v1 > bv1 || (v1 == bv1 && j < bj1)){ bv1 = v1; bj1 = j; }
    }
    #pragma unroll
    for(int o=16; o; o>>=1){
      float ov0 = __shfl_xor_sync(0xffffffffu, bv0, o);
      int   oj0 = __shfl_xor_sync(0xffffffffu, bj0, o);
      float ov1 = __shfl_xor_sync(0xffffffffu, bv1, o);
      int   oj1 = __shfl_xor_sync(0xffffffffu, bj1, o);
      if(ov0 > bv0 || (ov0 == bv0 && oj0 < bj0)){ bv0 = ov0; bj0 = oj0; }
      if(ov1 > bv1 || (ov1 == bv1 && oj1 < bj1)){ bv1 = ov1; bj1 = oj1; }
    }
    if(lane==0){
      d_topk[(node0+0)*Kk+sel] = bj0;
      d_topk[(node0+1)*Kk+sel] = bj1;
    }
    int sl0 = ((bj0>>7)<<2) | ((bj0>>5)&3);
    int sl1 = ((bj1>>7)<<2) | ((bj1>>5)&3);
    bool own0 = ((bj0 & 31) == lane);
    bool own1 = ((bj1 & 31) == lane);
    #pragma unroll
    for(int s=0; s<16; s++){
      if(own0 && s==sl0) sims0[s] = -INFINITY;
      if(own1 && s==sl1) sims1[s] = -INFINITY;
    }
  }
}

__device__ void gemm_body(char* gsm, int blk, const float* __restrict__ x,
                          const float* __restrict__ W,
                          const float* __restrict__ ati, const float* __restrict__ atj){
  __half* Xh = reinterpret_cast<__half*>(gsm + GS_XH);
  __half* Wh = reinterpret_cast<__half*>(gsm + GS_WH);
  float*  Cs = reinterpret_cast<float*>(gsm + GS_CS);
  __shared__ float s_si[128][2], s_sj[128][2];

  int t = threadIdx.x;

  const float2* W2 = reinterpret_cast<const float2*>(W);
  #pragma unroll
  for(int q=0; q<8; q++){
    int idx = q*256 + t;
    float2 wv = W2[idx];
    int r = idx >> 5, c2 = idx & 31;
    reinterpret_cast<__half2*>(Wh + r*72)[c2] = __floats2half2_rn(wv.x, wv.y);
  }
  const float2* X2 = reinterpret_cast<const float2*>(x + (size_t)blk*128*64);
  #pragma unroll
  for(int q=0; q<16; q++){
    int idx = q*256 + t;
    float2 xv = X2[idx];
    int r = idx >> 5, c2 = idx & 31;
    reinterpret_cast<__half2*>(Xh + r*72)[c2] = __floats2half2_rn(xv.x, xv.y);
  }
  __syncthreads();

  int w = t >> 5;
  wmma::fragment<wmma::accumulator,16,16,16,float> acc[4];
  #pragma unroll
  for(int n=0; n<4; n++) wmma::fill_fragment(acc[n], 0.0f);
  #pragma unroll
  for(int k=0; k<4; k++){
    wmma::fragment<wmma::matrix_a,16,16,16,__half,wmma::row_major> fa;
    wmma::load_matrix_sync(fa, Xh + (w*16)*72 + k*16, 72);
    #pragma unroll
    for(int n=0; n<4; n++){
      wmma::fragment<wmma::matrix_b,16,16,16,__half,wmma::row_major> fb;
      wmma::load_matrix_sync(fb, Wh + (k*16)*72 + n*16, 72);
      wmma::mma_sync(acc[n], fa, fb, acc[n]);
    }
  }
  #pragma unroll
  for(int n=0; n<4; n++)
    wmma::store_matrix_sync(Cs + (w*16)*68 + n*16, acc[n], 68, wmma::mem_row_major);
  __syncthreads();

  int row = t >> 1, hf = t & 1;
  const float* crow = Cs + row*68 + hf*32;
  float si = 0.f, sj = 0.f;
  union { __half2 h2[16]; uint4 u4[4]; } cv;
  #pragma unroll
  for(int q=0; q<8; q++){
    float4 c4 = *reinterpret_cast<const float4*>(crow + q*4);
    float4 av = *reinterpret_cast<const float4*>(ati + hf*32 + q*4);
    float4 aw = *reinterpret_cast<const float4*>(atj + hf*32 + q*4);
    si += c4.x*av.x + c4.y*av.y + c4.z*av.z + c4.w*av.w;
    sj += c4.x*aw.x + c4.y*aw.y + c4.z*aw.z + c4.w*aw.w;
    cv.h2[q*2]   = __floats2half2_rn(c4.x, c4.y);
    cv.h2[q*2+1] = __floats2half2_rn(c4.z, c4.w);
  }
  uint4* ghp = reinterpret_cast<uint4*>(d_gh2);
  int grow = blk*128 + row;
  #pragma unroll
  for(int q=0; q<4; q++) ghp[(size_t)grow*8 + hf*4 + q] = cv.u4[q];
  s_si[row][hf] = si; s_sj[row][hf] = sj;
  __syncthreads();
  if(t < 128){
    int gr = blk*128 + t;
    d_si[gr] = s_si[t][0] + s_si[t][1];   // eai added in k_attn
    d_sj[gr] = s_sj[t][0] + s_sj[t][1];
  }
}

__global__ void __launch_bounds__(256,3) k_work(const float* __restrict__ x,
                      const float* __restrict__ W,
                      const float* __restrict__ ati, const float* __restrict__ atj,
                      const float* __restrict__ embed,
                      const float* __restrict__ aemi, const float* __restrict__ aemj){
  extern __shared__ char gsm[];
  if(blockIdx.x < PRE_BLOCKS) pre_body(gsm, embed, aemi, aemj);
  else                        gemm_body(gsm, blockIdx.x - PRE_BLOCKS, x, W, ati, atj);
}

// ---- K2: 4 blocks/batch, 512 threads; fp16 g slice in smem; fp32 agg out ----
#define ATTN_SMEM_FLOATS (16384 + 512 + 128)   // gh(64KB) + sj + si
#define ATTN_SMEM_BYTES  (ATTN_SMEM_FLOATS*4)

__global__ void __launch_bounds__(512,3) k_attn(const float* __restrict__ gnn_bias){
  extern __shared__ float sm[];
  __half2* gh_sm = reinterpret_cast<__half2*>(sm);   // [src*32 + lane]
  float* sj_sm = sm + 16384;   // 512
  float* si_sm = sm + 16896;   // 128 (this block's rows)

  int t = threadIdx.x, lane = t & 31, w = t >> 5;
  int b  = blockIdx.x >> 2;
  int row0 = (blockIdx.x & 3) * 128;

  const uint4* s4 = reinterpret_cast<const uint4*>(d_gh2 + (size_t)b*16384);
  uint4* dst4 = reinterpret_cast<uint4*>(sm);
  #pragma unroll
  for(int q=0; q<8; q++) dst4[q*512+t] = s4[q*512+t];
  sj_sm[t] = d_sj[b*512+t] + d_eaj[t];
  if(t < 128) si_sm[t] = d_si[b*512 + row0 + t] + d_eai[row0 + t];
  __syncthreads();

  float2 bi2 = reinterpret_cast<const float2*>(gnn_bias)[lane];
  float2 ps = make_float2(0.f,0.f), pq = make_float2(0.f,0.f);

  for(int it=0; it<8; it++){
    int il = w*8 + it;            // local row 0..127
    int i  = row0 + il;           // node in batch
    unsigned packed;
    {
      int src = (lane < Kk) ? d_topk[i*Kk + lane] : i;  // lane 20 -> self
      float z;
      if(lane <= Kk){
        z = si_sm[il] + sj_sm[src];
        z = (z > 0.f) ? z : 0.2f*z;
        if(lane < Kk && src == i) z = -INFINITY;
      } else z = -INFINITY;
      float e = (lane <= Kk) ? __expf(z) : 0.f;   // no max-subtract (z bounded)
      float s = warpSum(e);
      float a = e / s;
      packed = (__float_as_uint(a) & 0xFFFFFE00u) | (unsigned)src;
    }
    float2 acc = make_float2(0.f,0.f);
    #pragma unroll
    for(int e=0; e<=Kk; e++){
      unsigned pk = __shfl_sync(0xffffffffu, packed, e);
      float a  = __uint_as_float(pk & 0xFFFFFE00u);
      int srow = (int)(pk & 511u);
      float2 v = __half22float2(gh_sm[srow*32 + lane]);
      acc.x += a*v.x; acc.y += a*v.y;
    }
    acc.x += bi2.x; acc.y += bi2.y;
    reinterpret_cast<float2*>(&d_agg[(size_t)(b*512+i)*64])[lane] = acc;
    ps.x += acc.x; ps.y += acc.y;
    pq.x += acc.x*acc.x; pq.y += acc.y*acc.y;
  }

  __syncthreads();
  float* rS = sm;          // 16*64
  float* rQ = sm + 1024;   // 16*64
  rS[w*64 + lane*2]   = ps.x;
  rS[w*64 + lane*2+1] = ps.y;
  rQ[w*64 + lane*2]   = pq.x;
  rQ[w*64 + lane*2+1] = pq.y;
  __syncthreads();
  if(t < 64){
    float S=0.f, Q=0.f;
    #pragma unroll
    for(int ww=0; ww<16; ww++){ S += rS[ww*64+t]; Q += rQ[ww*64+t]; }
    d_ps1[t*AGRID + blockIdx.x] = S;
    d_pq1[t*AGRID + blockIdx.x] = Q;
  }
}

// ---- K3: fused tail with agg smem cache (32KB dyn) ----
__device__ __forceinline__ void gridBarrier(){
  __threadfence();
  __syncthreads();
  if(threadIdx.x == 0){
    unsigned old = atomicAdd(&g_bar, 1u);
    unsigned target = (old/(unsigned)TGRID + 1u) * (unsigned)TGRID;
    while(((*(volatile unsigned*)&g_bar) - target) & 0x80000000u) __nanosleep(16);
  }
  __syncthreads();
}

__device__ __forceinline__ void reduceScale(const float* __restrict__ ps,
                                            const float* __restrict__ pq,
                                            int nblk,
                                            const float* __restrict__ gamma,
                                            const float* __restrict__ beta,
                                            float* __restrict__ scale,
                                            float* __restrict__ shift,
                                            float* shS, float* shQ){
  int c = blockIdx.x, t = threadIdx.x;
  float s = ps[c*nblk + t] + ps[c*nblk + t + 256];
  float q = pq[c*nblk + t] + pq[c*nblk + t + 256];
  s = warpSum(s); q = warpSum(q);
  if((t&31)==0){ shS[t>>5]=s; shQ[t>>5]=q; }
  __syncthreads();
  if(t==0){
    float S=0.f, Q=0.f;
    #pragma unroll
    for(int ww=0; ww<8; ww++){ S+=shS[ww]; Q+=shQ[ww]; }
    float mu  = S * (1.0f/(float)BN);
    float var = Q * (1.0f/(float)BN) - mu*mu;
    float sc  = gamma[c] * rsqrtf(var + 1e-5f);
    scale[c] = sc;
    shift[c] = beta[c] - mu*sc;
  }
}

#define TAIL_SMEM (2048*16)   // 2048 float4 agg cache = 32KB

__global__ void __launch_bounds__(256,4) k_tail(const float* __restrict__ embed,
                      const float* __restrict__ g1, const float* __restrict__ b1,
                      const float* __restrict__ g2, const float* __restrict__ b2,
                      const float* __restrict__ outW, const float* __restrict__ outB,
                      float* __restrict__ out){
  extern __shared__ float4 aggc[];          // 2048 float4 (this block's 128 rows)
  __shared__ float shp[1024], shq2[1024];
  int t = threadIdx.x;

  // phase 1: BN1 scale/shift (blocks 0..63)
  if(blockIdx.x < 64)
    reduceScale(d_ps1, d_pq1, AGRID, g1, b1, d_scale1, d_shift1, shp, shq2);
  gridBarrier();

  // phase 2: BN2 stats over h1 = relu(bn1(agg))*embed ; cache agg slice in smem
  {
    int d0 = (t & 15) * 4;
    float4 sc1 = *reinterpret_cast<const float4*>(&d_scale1[d0]);
    float4 sh1 = *reinterpret_cast<const float4*>(&d_shift1[d0]);
    float4 psum = make_float4(0.f,0.f,0.f,0.f);
    float4 psq  = make_float4(0.f,0.f,0.f,0.f);
    #pragma unroll
    for(int q=0; q<8; q++){
      int i = blockIdx.x*2048 + q*256 + t;   // (i&15)==(t&15)
      int row  = i >> 4;
      int node = row & (Nn-1);
      float4 a  = reinterpret_cast<const float4*>(d_agg)[i];
      aggc[q*256 + t] = a;
      float4 em = reinterpret_cast<const float4*>(embed)[node*16 + (t&15)];
      float4 r;
      r.x = fmaxf(a.x*sc1.x+sh1.x, 0.f)*em.x;
      r.y = fmaxf(a.y*sc1.y+sh1.y, 0.f)*em.y;
      r.z = fmaxf(a.z*sc1.z+sh1.z, 0.f)*em.z;
      r.w = fmaxf(a.w*sc1.w+sh1.w, 0.f)*em.w;
      psum.x += r.x; psum.y += r.y; psum.z += r.z; psum.w += r.w;
      psq.x += r.x*r.x; psq.y += r.y*r.y; psq.z += r.z*r.z; psq.w += r.w*r.w;
    }
    __syncthreads();
    shp[t*4+0]=psum.x; shp[t*4+1]=psum.y; shp[t*4+2]=psum.z; shp[t*4+3]=psum.w;
    shq2[t*4+0]=psq.x; shq2[t*4+1]=psq.y; shq2[t*4+2]=psq.z; shq2[t*4+3]=psq.w;
    __syncthreads();
    if(t < 64){
      int gi = t >> 2, comp = t & 3;
      float S=0.f, Q=0.f;
      #pragma unroll
      for(int m=0; m<16; m++){
        S += shp [(gi + m*16)*4 + comp];
        Q += shq2[(gi + m*16)*4 + comp];
      }
      d_ps2[t*TGRID + blockIdx.x] = S;
      d_pq2[t*TGRID + blockIdx.x] = Q;
    }
  }
  gridBarrier();

  // phase 3: BN2 scale/shift
  if(blockIdx.x < 64)
    reduceScale(d_ps2, d_pq2, TGRID, g2, b2, d_scale2, d_shift2, shp, shq2);
  gridBarrier();

  // phase 4: out from smem-cached agg
  {
    int sub = t & 15;
    float4 s1  = *reinterpret_cast<const float4*>(&d_scale1[sub*4]);
    float4 h1_ = *reinterpret_cast<const float4*>(&d_shift1[sub*4]);
    float4 s2  = *reinterpret_cast<const float4*>(&d_scale2[sub*4]);
    float4 h2_ = *reinterpret_cast<const float4*>(&d_shift2[sub*4]);
    float4 ow  = *reinterpret_cast<const float4*>(&outW[sub*4]);
    float ob = outB[0];
    #pragma unroll
    for(int it=0; it<8; it++){
      int row  = blockIdx.x*128 + it*16 + (t >> 4);
      int node = row & (Nn-1);
      float4 a  = aggc[it*256 + t];      // same layout as phase-2 store
      float4 em = *reinterpret_cast<const float4*>(&embed[node*64 + sub*4]);
      float hx = fmaxf(a.x*s1.x+h1_.x,0.f)*em.x;
      float hy = fmaxf(a.y*s1.y+h1_.y,0.f)*em.y;
      float hz = fmaxf(a.z*s1.z+h1_.z,0.f)*em.z;
      float hw = fmaxf(a.w*s1.w+h1_.w,0.f)*em.w;
      float p = fmaxf(hx*s2.x+h2_.x,0.f)*ow.x + fmaxf(hy*s2.y+h2_.y,0.f)*ow.y
              + fmaxf(hz*s2.z+h2_.z,0.f)*ow.z + fmaxf(hw*s2.w+h2_.w,0.f)*ow.w;
      #pragma unroll
      for(int o=8; o; o>>=1) p += __shfl_xor_sync(0xffffffffu, p, o);
      if(sub==0) out[row] = p + ob;
    }
  }
}

extern "C" void kernel_launch(void* const* d_in, const int* in_sizes, int n_in,
                              void* d_out, int out_size){
  int iData, iEmbed, iW, iAtI, iAtJ, iAemI, iAemJ, iBias, iG1, iB1, iG2, iB2, iOW, iOB;
  if(n_in >= 15 && in_sizes[1] == 2048){
    iData=0; iEmbed=2; iW=3; iAtI=4; iAtJ=5; iAemI=6; iAemJ=7; iBias=8;
    iG1=9; iB1=10; iG2=11; iB2=12; iOW=13; iOB=14;
  } else {
    iData=0; iEmbed=1; iW=2; iAtI=3; iAtJ=4; iAemI=5; iAemJ=6; iBias=7;
    iG1=8; iB1=9; iG2=10; iB2=11; iOW=12; iOB=13;
  }
  const float* data  = (const float*)d_in[iData];
  const float* embed = (const float*)d_in[iEmbed];
  const float* W     = (const float*)d_in[iW];
  const float* atI   = (const float*)d_in[iAtI];
  const float* atJ   = (const float*)d_in[iAtJ];
  const float* aemI  = (const float*)d_in[iAemI];
  const float* aemJ  = (const float*)d_in[iAemJ];
  const float* bias  = (const float*)d_in[iBias];
  const float* g1    = (const float*)d_in[iG1];
  const float* b1    = (const float*)d_in[iB1];
  const float* g2    = (const float*)d_in[iG2];
  const float* b2    = (const float*)d_in[iB2];
  const float* outW  = (const float*)d_in[iOW];
  const float* outB  = (const float*)d_in[iOB];
  float* out = (float*)d_out;

  cudaFuncSetAttribute(k_work, cudaFuncAttributeMaxDynamicSharedMemorySize, WORK_SMEM);
  cudaFuncSetAttribute(k_attn, cudaFuncAttributeMaxDynamicSharedMemorySize, ATTN_SMEM_BYTES);
  cudaFuncSetAttribute(k_tail, cudaFuncAttributeMaxDynamicSharedMemorySize, TAIL_SMEM);

  k_work <<<PRE_BLOCKS + BN/128, 256, WORK_SMEM>>>(data, W, atI, atJ, embed, aemI, aemJ);
  k_attn <<<AGRID, 512, ATTN_SMEM_BYTES>>>(bias);
  k_tail <<<TGRID, 256, TAIL_SMEM>>>(embed, g1, b1, g2, b2, outW, outB, out);
}

// round 15
// speedup vs baseline: 1.1141x; 1.1141x over previous
#include <cuda_runtime.h>
#include <cuda_fp16.h>
#include <mma.h>
#include <math.h>

using namespace nvcuda;

#define Bsz 128
#define Nn  512
#define Ff  64
#define Dd  64
#define Kk  20
#define BN  (Bsz*Nn)          // 65536
#define NELEM (BN*Dd)         // 4194304
#define GB_N 256              // attn_tail grid (persistent, all resident)
#define PRE_BLOCKS 64

// ---------------- device scratch (no allocations allowed) ----------------
__device__ __half2 d_gh2[NELEM/2];        // g in fp16, [row][64]
__device__ float d_agg[NELEM];            // agg fp32
__device__ float d_si[BN];
__device__ float d_sj[BN];
__device__ float d_eai[Nn];
__device__ float d_eaj[Nn];
__device__ int   d_topk[Nn*Kk];
__device__ float d_ps1[64*GB_N];          // channel-major BN1 partials
__device__ float d_pq1[64*GB_N];
__device__ float d_ps2[64*GB_N];          // channel-major BN2 partials
__device__ float d_pq2[64*GB_N];
__device__ float d_scale1[64], d_shift1[64], d_scale2[64], d_shift2[64];
__device__ unsigned g_bar;                // monotonic grid-barrier counter

__device__ __forceinline__ float warpSum(float v){
  #pragma unroll
  for(int o=16;o;o>>=1) v += __shfl_xor_sync(0xffffffffu, v, o);
  return v;
}

// ==== fused work kernel: blocks 0-63 -> pre(topk), blocks 64-575 -> gemm ====
#define GS_XH 0
#define GS_WH 18432
#define GS_CS 27648
#define WORK_SMEM (27648 + 128*68*4)   // 62464 bytes

// pre: 8 warps, 1 node each; precomputed inv-norms; double-buffered chunks.
__device__ void pre_body(char* gsm, const float* __restrict__ embed,
                         const float* __restrict__ aemi,
                         const float* __restrict__ aemj){
  float* tile0 = reinterpret_cast<float*>(gsm);   // 64*68
  float* tile1 = tile0 + 64*68;                   // 64*68
  float* srows = tile1 + 64*68;                   // 8*68
  float* invn  = srows + 8*68;                    // 512
  int t = threadIdx.x, w = t>>5, lane = t&31;
  int node = blockIdx.x*8 + w;

  // step 0: inverse norms for all 512 rows (thread t -> rows 2t, 2t+1)
  #pragma unroll
  for(int rr=0; rr<2; rr++){
    int row = t*2 + rr;
    const float4* er = reinterpret_cast<const float4*>(embed + row*64);
    float ss = 0.f;
    #pragma unroll
    for(int q=0;q<16;q++){ float4 v=er[q]; ss += v.x*v.x+v.y*v.y+v.z*v.z+v.w*v.w; }
    invn[row] = 1.0f/(sqrtf(ss)+1e-12f);
  }
  // own 8 rows raw
  if(t < 128){
    int r = t >> 4, c4 = t & 15;
    float4 v = reinterpret_cast<const float4*>(embed)[(blockIdx.x*8 + r)*16 + c4];
    *reinterpret_cast<float4*>(&srows[r*68 + c4*4]) = v;
  }
  __syncthreads();
  // eai/eaj from raw row, then normalize own srow (own-warp only; no sync needed)
  {
    float v0 = srows[w*68+lane], v1 = srows[w*68+32+lane];
    float si = warpSum(v0*aemi[lane] + v1*aemi[lane+32]);
    float sj = warpSum(v0*aemj[lane] + v1*aemj[lane+32]);
    if(lane==0){ d_eai[node]=si; d_eaj[node]=sj; }
    float inv = invn[node];
    srows[w*68+lane]    = v0*inv;
    srows[w*68+32+lane] = v1*inv;
  }
  // preload chunk 0
  float4 vld[4]; float ivld[4];
  #pragma unroll
  for(int q=0;q<4;q++){
    int idx = q*256 + t; int r = idx >> 4;
    vld[q]  = reinterpret_cast<const float4*>(embed)[r*16 + (idx&15)];
    ivld[q] = invn[r];
  }

  float sims[16];
  for(int c=0;c<8;c++){
    float* cur = (c&1) ? tile1 : tile0;
    #pragma unroll
    for(int q=0;q<4;q++){
      int idx = q*256 + t; int r = idx >> 4;
      float4 v = vld[q]; float iv = ivld[q];
      v.x*=iv; v.y*=iv; v.z*=iv; v.w*=iv;
      *reinterpret_cast<float4*>(&cur[r*68 + (idx&15)*4]) = v;
    }
    __syncthreads();
    if(c < 7){
      #pragma unroll
      for(int q=0;q<4;q++){
        int idx = q*256 + t; int r = idx >> 4;
        vld[q]  = reinterpret_cast<const float4*>(embed)[((c+1)*64 + r)*16 + (idx&15)];
        ivld[q] = invn[(c+1)*64 + r];
      }
    }
    const float* sr = &srows[w*68];
    float a0 = 0.f, a1 = 0.f;
    #pragma unroll
    for(int kk=0; kk<64; kk+=4){
      float4 s4 = *reinterpret_cast<const float4*>(&sr[kk]);
      float4 e0 = *reinterpret_cast<const float4*>(&cur[lane*68+kk]);
      float4 e1 = *reinterpret_cast<const float4*>(&cur[(lane+32)*68+kk]);
      a0 += s4.x*e0.x + s4.y*e0.y + s4.z*e0.z + s4.w*e0.w;
      a1 += s4.x*e1.x + s4.y*e1.y + s4.z*e1.z + s4.w*e1.w;
    }
    sims[c*2]   = a0;
    sims[c*2+1] = a1;
    __syncthreads();
  }

  for(int sel=0; sel<Kk; sel++){
    float bv = -INFINITY; int bj = 0x3fffffff;
    #pragma unroll
    for(int s=0; s<16; s++){
      float v = sims[s];
      int j = (s>>1)*64 + (s&1)*32 + lane;
      if(v > bv || (v == bv && j < bj)){ bv = v; bj = j; }
    }
    #pragma unroll
    for(int o=16; o; o>>=1){
      float ov = __shfl_xor_sync(0xffffffffu, bv, o);
      int   oj = __shfl_xor_sync(0xffffffffu, bj, o);
      if(ov > bv || (ov == bv && oj < bj)){ bv = ov; bj = oj; }
    }
    if(lane==0) d_topk[node*Kk+sel] = bj;
    int wslot = ((bj>>6)<<1) | ((bj>>5)&1);
    bool own = ((bj & 31) == lane);
    #pragma unroll
    for(int s=0; s<16; s++) if(own && s==wslot) sims[s] = -INFINITY;
  }
}

__device__ void gemm_body(char* gsm, int blk, const float* __restrict__ x,
                          const float* __restrict__ W,
                          const float* __restrict__ ati, const float* __restrict__ atj){
  __half* Xh = reinterpret_cast<__half*>(gsm + GS_XH);
  __half* Wh = reinterpret_cast<__half*>(gsm + GS_WH);
  float*  Cs = reinterpret_cast<float*>(gsm + GS_CS);
  __shared__ float s_si[128][2], s_sj[128][2];

  int t = threadIdx.x;

  const float4* W4 = reinterpret_cast<const float4*>(W);
  #pragma unroll
  for(int q=0; q<4; q++){
    int idx = q*256 + t;               // 1024 float4 = 4096 floats
    float4 wv = W4[idx];
    int r = idx >> 4, c4 = idx & 15;
    __half2* dst = reinterpret_cast<__half2*>(Wh + r*72);
    dst[c4*2]   = __floats2half2_rn(wv.x, wv.y);
    dst[c4*2+1] = __floats2half2_rn(wv.z, wv.w);
  }
  const float4* X4 = reinterpret_cast<const float4*>(x + (size_t)blk*128*64);
  #pragma unroll
  for(int q=0; q<8; q++){
    int idx = q*256 + t;               // 2048 float4 = 8192 floats
    float4 xv = X4[idx];
    int r = idx >> 4, c4 = idx & 15;
    __half2* dst = reinterpret_cast<__half2*>(Xh + r*72);
    dst[c4*2]   = __floats2half2_rn(xv.x, xv.y);
    dst[c4*2+1] = __floats2half2_rn(xv.z, xv.w);
  }
  __syncthreads();

  int w = t >> 5;
  wmma::fragment<wmma::accumulator,16,16,16,float> acc[4];
  #pragma unroll
  for(int n=0; n<4; n++) wmma::fill_fragment(acc[n], 0.0f);
  #pragma unroll
  for(int k=0; k<4; k++){
    wmma::fragment<wmma::matrix_a,16,16,16,__half,wmma::row_major> fa;
    wmma::load_matrix_sync(fa, Xh + (w*16)*72 + k*16, 72);
    #pragma unroll
    for(int n=0; n<4; n++){
      wmma::fragment<wmma::matrix_b,16,16,16,__half,wmma::row_major> fb;
      wmma::load_matrix_sync(fb, Wh + (k*16)*72 + n*16, 72);
      wmma::mma_sync(acc[n], fa, fb, acc[n]);
    }
  }
  #pragma unroll
  for(int n=0; n<4; n++)
    wmma::store_matrix_sync(Cs + (w*16)*68 + n*16, acc[n], 68, wmma::mem_row_major);
  __syncthreads();

  int row = t >> 1, hf = t & 1;
  const float* crow = Cs + row*68 + hf*32;
  float si = 0.f, sj = 0.f;
  union { __half2 h2[16]; uint4 u4[4]; } cv;
  #pragma unroll
  for(int q=0; q<8; q++){
    float4 c4 = *reinterpret_cast<const float4*>(crow + q*4);
    float4 av = *reinterpret_cast<const float4*>(ati + hf*32 + q*4);
    float4 aw = *reinterpret_cast<const float4*>(atj + hf*32 + q*4);
    si += c4.x*av.x + c4.y*av.y + c4.z*av.z + c4.w*av.w;
    sj += c4.x*aw.x + c4.y*aw.y + c4.z*aw.z + c4.w*aw.w;
    cv.h2[q*2]   = __floats2half2_rn(c4.x, c4.y);
    cv.h2[q*2+1] = __floats2half2_rn(c4.z, c4.w);
  }
  uint4* ghp = reinterpret_cast<uint4*>(d_gh2);
  int grow = blk*128 + row;
  #pragma unroll
  for(int q=0; q<4; q++) ghp[(size_t)grow*8 + hf*4 + q] = cv.u4[q];
  s_si[row][hf] = si; s_sj[row][hf] = sj;
  __syncthreads();
  if(t < 128){
    int gr = blk*128 + t;
    d_si[gr] = s_si[t][0] + s_si[t][1];   // eai added in attn
    d_sj[gr] = s_sj[t][0] + s_sj[t][1];
  }
}

__global__ void __launch_bounds__(256,3) k_work(const float* __restrict__ x,
                      const float* __restrict__ W,
                      const float* __restrict__ ati, const float* __restrict__ atj,
                      const float* __restrict__ embed,
                      const float* __restrict__ aemi, const float* __restrict__ aemj){
  extern __shared__ char gsm[];
  if(blockIdx.x < PRE_BLOCKS) pre_body(gsm, embed, aemi, aemj);
  else                        gemm_body(gsm, blockIdx.x - PRE_BLOCKS, x, W, ati, atj);
}

// ==== merged attn + tail: 256 persistent blocks x 512 threads ====
// dyn smem floats: g(16384) + sj(512) + si(256) = 17152 -> 68608 B
#define AT_SMEM_FLOATS (16384 + 512 + 256)
#define AT_SMEM_BYTES  (AT_SMEM_FLOATS*4)

__device__ __forceinline__ void gridBarrier256(){
  __threadfence();
  __syncthreads();
  if(threadIdx.x == 0){
    unsigned old = atomicAdd(&g_bar, 1u);
    unsigned target = (old/(unsigned)GB_N + 1u) * (unsigned)GB_N;
    while(((*(volatile unsigned*)&g_bar) - target) & 0x80000000u) __nanosleep(16);
  }
  __syncthreads();
}

__device__ __forceinline__ void reduceScale256(const float* __restrict__ ps,
                                               const float* __restrict__ pq,
                                               const float* __restrict__ gamma,
                                               const float* __restrict__ beta,
                                               float* __restrict__ scale,
                                               float* __restrict__ shift){
  __shared__ float shS[16], shQ[16];
  int c = blockIdx.x, t = threadIdx.x, w = t>>5;
  float s = (t < GB_N) ? ps[c*GB_N + t] : 0.f;
  float q = (t < GB_N) ? pq[c*GB_N + t] : 0.f;
  s = warpSum(s); q = warpSum(q);
  if((t&31)==0){ shS[w]=s; shQ[w]=q; }
  __syncthreads();
  if(t==0){
    float S=0.f, Q=0.f;
    #pragma unroll
    for(int ww=0; ww<16; ww++){ S+=shS[ww]; Q+=shQ[ww]; }
    float mu  = S * (1.0f/(float)BN);
    float var = Q * (1.0f/(float)BN) - mu*mu;
    float sc  = gamma[c] * rsqrtf(var + 1e-5f);
    scale[c] = sc;
    shift[c] = beta[c] - mu*sc;
  }
  __syncthreads();
}

__global__ void __launch_bounds__(512,2) k_attn_tail(
                      const float* __restrict__ gnn_bias,
                      const float* __restrict__ embed,
                      const float* __restrict__ g1, const float* __restrict__ b1,
                      const float* __restrict__ g2, const float* __restrict__ b2,
                      const float* __restrict__ outW, const float* __restrict__ outB,
                      float* __restrict__ out){
  extern __shared__ float sm[];
  __half2* gh_sm = reinterpret_cast<__half2*>(sm);   // [src*32 + lane]
  float* sj_sm = sm + 16384;   // 512
  float* si_sm = sm + 16896;   // 256

  int t = threadIdx.x, lane = t & 31, w = t >> 5;
  int b        = blockIdx.x >> 1;
  int row_base = (blockIdx.x & 1) * 256;

  const uint4* s4 = reinterpret_cast<const uint4*>(d_gh2 + (size_t)b*16384);
  uint4* dst4 = reinterpret_cast<uint4*>(sm);
  #pragma unroll
  for(int q=0; q<8; q++) dst4[q*512+t] = s4[q*512+t];
  sj_sm[t] = d_sj[b*512+t] + d_eaj[t];
  if(t < 256) si_sm[t] = d_si[b*512 + row_base + t] + d_eai[row_base + t];
  __syncthreads();

  float2 bi2 = reinterpret_cast<const float2*>(gnn_bias)[lane];
  float2 ps = make_float2(0.f,0.f), pq = make_float2(0.f,0.f);

  #pragma unroll
  for(int tl=0; tl<2; tl++){
    for(int it=0; it<8; it++){
      int lr = tl*128 + w*8 + it;     // local row 0..255
      int i  = row_base + lr;         // node in batch
      unsigned packed;
      {
        int src = (lane < Kk) ? d_topk[i*Kk + lane] : i;
        float z;
        if(lane <= Kk){
          z = si_sm[lr] + sj_sm[src];
          z = (z > 0.f) ? z : 0.2f*z;
          if(lane < Kk && src == i) z = -INFINITY;
        } else z = -INFINITY;
        float e = (lane <= Kk) ? __expf(z) : 0.f;
        float s = warpSum(e);
        float a = e / s;
        packed = (__float_as_uint(a) & 0xFFFFFE00u) | (unsigned)src;
      }
      float2 acc = make_float2(0.f,0.f);
      #pragma unroll
      for(int e=0; e<=Kk; e++){
        unsigned pk = __shfl_sync(0xffffffffu, packed, e);
        float a  = __uint_as_float(pk & 0xFFFFFE00u);
        int srow = (int)(pk & 511u);
        float2 v = __half22float2(gh_sm[srow*32 + lane]);
        acc.x += a*v.x; acc.y += a*v.y;
      }
      acc.x += bi2.x; acc.y += bi2.y;
      reinterpret_cast<float2*>(&d_agg[(size_t)(b*512+i)*64])[lane] = acc;
      ps.x += acc.x; ps.y += acc.y;
      pq.x += acc.x*acc.x; pq.y += acc.y*acc.y;
    }
  }

  // BN1 partials (alias dead g region)
  __syncthreads();
  {
    float* rS = sm;          // 16*64
    float* rQ = sm + 1024;
    rS[w*64 + lane*2]   = ps.x;
    rS[w*64 + lane*2+1] = ps.y;
    rQ[w*64 + lane*2]   = pq.x;
    rQ[w*64 + lane*2+1] = pq.y;
    __syncthreads();
    if(t < 64){
      float S=0.f, Q=0.f;
      #pragma unroll
      for(int ww=0; ww<16; ww++){ S += sm[ww*64+t]; Q += sm[1024 + ww*64+t]; }
      d_ps1[t*GB_N + blockIdx.x] = S;
      d_pq1[t*GB_N + blockIdx.x] = Q;
    }
  }
  gridBarrier256();

  // phase 1: BN1 scale/shift (blocks 0..63)
  if(blockIdx.x < 64)
    reduceScale256(d_ps1, d_pq1, g1, b1, d_scale1, d_shift1);
  gridBarrier256();

  // phase 2: BN2 stats over own 256 rows (4096 float4); partials in dead g region
  {
    float* shp  = sm;          // 2048
    float* shq2 = sm + 2048;   // 2048
    int d0 = (t & 15) * 4;
    float4 sc1 = *reinterpret_cast<const float4*>(&d_scale1[d0]);
    float4 sh1 = *reinterpret_cast<const float4*>(&d_shift1[d0]);
    float4 psum = make_float4(0.f,0.f,0.f,0.f);
    float4 psq  = make_float4(0.f,0.f,0.f,0.f);
    #pragma unroll
    for(int q=0; q<8; q++){
      int i = blockIdx.x*4096 + q*512 + t;   // (i&15)==(t&15)
      int row  = i >> 4;
      int node = row & (Nn-1);
      float4 a  = reinterpret_cast<const float4*>(d_agg)[i];
      float4 em = reinterpret_cast<const float4*>(embed)[node*16 + (t&15)];
      float4 r;
      r.x = fmaxf(a.x*sc1.x+sh1.x, 0.f)*em.x;
      r.y = fmaxf(a.y*sc1.y+sh1.y, 0.f)*em.y;
      r.z = fmaxf(a.z*sc1.z+sh1.z, 0.f)*em.z;
      r.w = fmaxf(a.w*sc1.w+sh1.w, 0.f)*em.w;
      psum.x += r.x; psum.y += r.y; psum.z += r.z; psum.w += r.w;
      psq.x += r.x*r.x; psq.y += r.y*r.y; psq.z += r.z*r.z; psq.w += r.w*r.w;
    }
    __syncthreads();
    shp[t*4+0]=psum.x; shp[t*4+1]=psum.y; shp[t*4+2]=psum.z; shp[t*4+3]=psum.w;
    shq2[t*4+0]=psq.x; shq2[t*4+1]=psq.y; shq2[t*4+2]=psq.z; shq2[t*4+3]=psq.w;
    __syncthreads();
    if(t < 64){
      int grp = t >> 2, comp = t & 3;   // channel = grp*4+comp
      float S=0.f, Q=0.f;
      #pragma unroll
      for(int m=0; m<32; m++){
        S += shp [(grp + m*16)*4 + comp];
        Q += shq2[(grp + m*16)*4 + comp];
      }
      d_ps2[t*GB_N + blockIdx.x] = S;
      d_pq2[t*GB_N + blockIdx.x] = Q;
    }
  }
  gridBarrier256();

  // phase 3: BN2 scale/shift
  if(blockIdx.x < 64)
    reduceScale256(d_ps2, d_pq2, g2, b2, d_scale2, d_shift2);
  gridBarrier256();

  // phase 4: out over own 256 rows
  {
    int sub = t & 15;
    float4 s1  = *reinterpret_cast<const float4*>(&d_scale1[sub*4]);
    float4 h1_ = *reinterpret_cast<const float4*>(&d_shift1[sub*4]);
    float4 s2  = *reinterpret_cast<const float4*>(&d_scale2[sub*4]);
    float4 h2_ = *reinterpret_cast<const float4*>(&d_shift2[sub*4]);
    float4 ow  = *reinterpret_cast<const float4*>(&outW[sub*4]);
    float ob = outB[0];
    #pragma unroll
    for(int it=0; it<8; it++){
      int row  = blockIdx.x*256 + it*32 + (t >> 4);
      int node = row & (Nn-1);
      float4 a  = *reinterpret_cast<const float4*>(&d_agg[(size_t)row*64 + sub*4]);
      float4 em = *reinterpret_cast<const float4*>(&embed[node*64 + sub*4]);
      float hx = fmaxf(a.x*s1.x+h1_.x,0.f)*em.x;
      float hy = fmaxf(a.y*s1.y+h1_.y,0.f)*em.y;
      float hz = fmaxf(a.z*s1.z+h1_.z,0.f)*em.z;
      float hw = fmaxf(a.w*s1.w+h1_.w,0.f)*em.w;
      float p = fmaxf(hx*s2.x+h2_.x,0.f)*ow.x + fmaxf(hy*s2.y+h2_.y,0.f)*ow.y
              + fmaxf(hz*s2.z+h2_.z,0.f)*ow.z + fmaxf(hw*s2.w+h2_.w,0.f)*ow.w;
      #pragma unroll
      for(int o=8; o; o>>=1) p += __shfl_xor_sync(0xffffffffu, p, o);
      if(sub==0) out[row] = p + ob;
    }
  }
}

extern "C" void kernel_launch(void* const* d_in, const int* in_sizes, int n_in,
                              void* d_out, int out_size){
  int iData, iEmbed, iW, iAtI, iAtJ, iAemI, iAemJ, iBias, iG1, iB1, iG2, iB2, iOW, iOB;
  if(n_in >= 15 && in_sizes[1] == 2048){
    iData=0; iEmbed=2; iW=3; iAtI=4; iAtJ=5; iAemI=6; iAemJ=7; iBias=8;
    iG1=9; iB1=10; iG2=11; iB2=12; iOW=13; iOB=14;
  } else {
    iData=0; iEmbed=1; iW=2; iAtI=3; iAtJ=4; iAemI=5; iAemJ=6; iBias=7;
    iG1=8; iB1=9; iG2=10; iB2=11; iOW=12; iOB=13;
  }
  const float* data  = (const float*)d_in[iData];
  const float* embed = (const float*)d_in[iEmbed];
  const float* W     = (const float*)d_in[iW];
  const float* atI   = (const float*)d_in[iAtI];
  const float* atJ   = (const float*)d_in[iAtJ];
  const float* aemI  = (const float*)d_in[iAemI];
  const float* aemJ  = (const float*)d_in[iAemJ];
  const float* bias  = (const float*)d_in[iBias];
  const float* g1    = (const float*)d_in[iG1];
  const float* b1    = (const float*)d_in[iB1];
  const float* g2    = (const float*)d_in[iG2];
  const float* b2    = (const float*)d_in[iB2];
  const float* outW  = (const float*)d_in[iOW];
  const float* outB  = (const float*)d_in[iOB];
  float* out = (float*)d_out;

  cudaFuncSetAttribute(k_work, cudaFuncAttributeMaxDynamicSharedMemorySize, WORK_SMEM);
  cudaFuncSetAttribute(k_attn_tail, cudaFuncAttributeMaxDynamicSharedMemorySize, AT_SMEM_BYTES);

  k_work <<<PRE_BLOCKS + BN/128, 256, WORK_SMEM>>>(data, W, atI, atJ, embed, aemI, aemJ);
  k_attn_tail <<<GB_N, 512, AT_SMEM_BYTES>>>(bias, embed, g1, b1, g2, b2, outW, outB, out);
}

// round 16
// speedup vs baseline: 1.1913x; 1.0693x over previous
#include <cuda_runtime.h>
#include <cuda_fp16.h>
#include <mma.h>
#include <math.h>

using namespace nvcuda;

#define Bsz 128
#define Nn  512
#define Ff  64
#define Dd  64
#define Kk  20
#define BN  (Bsz*Nn)          // 65536
#define NELEM (BN*Dd)         // 4194304
#define GB_N 256              // attn_tail grid (persistent, all resident)
#define PRE_BLOCKS 64

// ---------------- device scratch (no allocations allowed) ----------------
__device__ __half2 d_gh2[NELEM/2];        // g in fp16, [row][64]
__device__ float d_agg[NELEM];            // agg fp32
__device__ float d_si[BN];
__device__ float d_sj[BN];
__device__ float d_eai[Nn];
__device__ float d_eaj[Nn];
__device__ int   d_topk[Nn*Kk];
__device__ float d_ps1[64*GB_N];          // channel-major BN1 partials
__device__ float d_pq1[64*GB_N];
__device__ float d_ps2[64*GB_N];          // channel-major BN2 partials
__device__ float d_pq2[64*GB_N];
__device__ float d_scale1[64], d_shift1[64], d_scale2[64], d_shift2[64];
__device__ unsigned g_bar;                // monotonic grid-barrier counter

__device__ __forceinline__ float warpSum(float v){
  #pragma unroll
  for(int o=16;o;o>>=1) v += __shfl_xor_sync(0xffffffffu, v, o);
  return v;
}

// ==== fused work kernel: blocks 0-63 -> pre(topk), blocks 64-575 -> gemm ====
#define GS_XH 0
#define GS_WH 18432
#define GS_CS 27648
#define WORK_SMEM (27648 + 128*68*4)   // 62464 bytes

// pre: 8 warps, 1 node each; precomputed inv-norms; double-buffered chunks.
__device__ void pre_body(char* gsm, const float* __restrict__ embed,
                         const float* __restrict__ aemi,
                         const float* __restrict__ aemj){
  float* tile0 = reinterpret_cast<float*>(gsm);   // 64*68
  float* tile1 = tile0 + 64*68;                   // 64*68
  float* srows = tile1 + 64*68;                   // 8*68
  float* invn  = srows + 8*68;                    // 512
  int t = threadIdx.x, w = t>>5, lane = t&31;
  int node = blockIdx.x*8 + w;

  // step 0: inverse norms for all 512 rows (thread t -> rows 2t, 2t+1)
  #pragma unroll
  for(int rr=0; rr<2; rr++){
    int row = t*2 + rr;
    const float4* er = reinterpret_cast<const float4*>(embed + row*64);
    float ss = 0.f;
    #pragma unroll
    for(int q=0;q<16;q++){ float4 v=er[q]; ss += v.x*v.x+v.y*v.y+v.z*v.z+v.w*v.w; }
    invn[row] = 1.0f/(sqrtf(ss)+1e-12f);
  }
  // own 8 rows raw
  if(t < 128){
    int r = t >> 4, c4 = t & 15;
    float4 v = reinterpret_cast<const float4*>(embed)[(blockIdx.x*8 + r)*16 + c4];
    *reinterpret_cast<float4*>(&srows[r*68 + c4*4]) = v;
  }
  __syncthreads();
  // eai/eaj from raw row, then normalize own srow
  {
    float v0 = srows[w*68+lane], v1 = srows[w*68+32+lane];
    float si = warpSum(v0*aemi[lane] + v1*aemi[lane+32]);
    float sj = warpSum(v0*aemj[lane] + v1*aemj[lane+32]);
    if(lane==0){ d_eai[node]=si; d_eaj[node]=sj; }
    float inv = invn[node];
    srows[w*68+lane]    = v0*inv;
    srows[w*68+32+lane] = v1*inv;
  }
  // preload chunk 0
  float4 vld[4]; float ivld[4];
  #pragma unroll
  for(int q=0;q<4;q++){
    int idx = q*256 + t; int r = idx >> 4;
    vld[q]  = reinterpret_cast<const float4*>(embed)[r*16 + (idx&15)];
    ivld[q] = invn[r];
  }

  float sims[16];
  for(int c=0;c<8;c++){
    float* cur = (c&1) ? tile1 : tile0;
    #pragma unroll
    for(int q=0;q<4;q++){
      int idx = q*256 + t; int r = idx >> 4;
      float4 v = vld[q]; float iv = ivld[q];
      v.x*=iv; v.y*=iv; v.z*=iv; v.w*=iv;
      *reinterpret_cast<float4*>(&cur[r*68 + (idx&15)*4]) = v;
    }
    __syncthreads();
    if(c < 7){
      #pragma unroll
      for(int q=0;q<4;q++){
        int idx = q*256 + t; int r = idx >> 4;
        vld[q]  = reinterpret_cast<const float4*>(embed)[((c+1)*64 + r)*16 + (idx&15)];
        ivld[q] = invn[(c+1)*64 + r];
      }
    }
    const float* sr = &srows[w*68];
    float a0 = 0.f, a1 = 0.f;
    #pragma unroll
    for(int kk=0; kk<64; kk+=4){
      float4 s4 = *reinterpret_cast<const float4*>(&sr[kk]);
      float4 e0 = *reinterpret_cast<const float4*>(&cur[lane*68+kk]);
      float4 e1 = *reinterpret_cast<const float4*>(&cur[(lane+32)*68+kk]);
      a0 += s4.x*e0.x + s4.y*e0.y + s4.z*e0.z + s4.w*e0.w;
      a1 += s4.x*e1.x + s4.y*e1.y + s4.z*e1.z + s4.w*e1.w;
    }
    sims[c*2]   = a0;
    sims[c*2+1] = a1;
    __syncthreads();
  }

  for(int sel=0; sel<Kk; sel++){
    float bv = -INFINITY; int bj = 0x3fffffff;
    #pragma unroll
    for(int s=0; s<16; s++){
      float v = sims[s];
      int j = (s>>1)*64 + (s&1)*32 + lane;
      if(v > bv || (v == bv && j < bj)){ bv = v; bj = j; }
    }
    #pragma unroll
    for(int o=16; o; o>>=1){
      float ov = __shfl_xor_sync(0xffffffffu, bv, o);
      int   oj = __shfl_xor_sync(0xffffffffu, bj, o);
      if(ov > bv || (ov == bv && oj < bj)){ bv = ov; bj = oj; }
    }
    if(lane==0) d_topk[node*Kk+sel] = bj;
    int wslot = ((bj>>6)<<1) | ((bj>>5)&1);
    bool own = ((bj & 31) == lane);
    #pragma unroll
    for(int s=0; s<16; s++) if(own && s==wslot) sims[s] = -INFINITY;
  }
}

__device__ void gemm_body(char* gsm, int blk, const float* __restrict__ x,
                          const float* __restrict__ W,
                          const float* __restrict__ ati, const float* __restrict__ atj){
  __half* Xh = reinterpret_cast<__half*>(gsm + GS_XH);
  __half* Wh = reinterpret_cast<__half*>(gsm + GS_WH);
  float*  Cs = reinterpret_cast<float*>(gsm + GS_CS);
  __shared__ float s_si[128][2], s_sj[128][2];

  int t = threadIdx.x;

  const float4* W4 = reinterpret_cast<const float4*>(W);
  #pragma unroll
  for(int q=0; q<4; q++){
    int idx = q*256 + t;
    float4 wv = W4[idx];
    int r = idx >> 4, c4 = idx & 15;
    __half2* dst = reinterpret_cast<__half2*>(Wh + r*72);
    dst[c4*2]   = __floats2half2_rn(wv.x, wv.y);
    dst[c4*2+1] = __floats2half2_rn(wv.z, wv.w);
  }
  const float4* X4 = reinterpret_cast<const float4*>(x + (size_t)blk*128*64);
  #pragma unroll
  for(int q=0; q<8; q++){
    int idx = q*256 + t;
    float4 xv = X4[idx];
    int r = idx >> 4, c4 = idx & 15;
    __half2* dst = reinterpret_cast<__half2*>(Xh + r*72);
    dst[c4*2]   = __floats2half2_rn(xv.x, xv.y);
    dst[c4*2+1] = __floats2half2_rn(xv.z, xv.w);
  }
  __syncthreads();

  int w = t >> 5;
  wmma::fragment<wmma::accumulator,16,16,16,float> acc[4];
  #pragma unroll
  for(int n=0; n<4; n++) wmma::fill_fragment(acc[n], 0.0f);
  #pragma unroll
  for(int k=0; k<4; k++){
    wmma::fragment<wmma::matrix_a,16,16,16,__half,wmma::row_major> fa;
    wmma::load_matrix_sync(fa, Xh + (w*16)*72 + k*16, 72);
    #pragma unroll
    for(int n=0; n<4; n++){
      wmma::fragment<wmma::matrix_b,16,16,16,__half,wmma::row_major> fb;
      wmma::load_matrix_sync(fb, Wh + (k*16)*72 + n*16, 72);
      wmma::mma_sync(acc[n], fa, fb, acc[n]);
    }
  }
  #pragma unroll
  for(int n=0; n<4; n++)
    wmma::store_matrix_sync(Cs + (w*16)*68 + n*16, acc[n], 68, wmma::mem_row_major);
  __syncthreads();

  int row = t >> 1, hf = t & 1;
  const float* crow = Cs + row*68 + hf*32;
  float si = 0.f, sj = 0.f;
  union { __half2 h2[16]; uint4 u4[4]; } cv;
  #pragma unroll
  for(int q=0; q<8; q++){
    float4 c4 = *reinterpret_cast<const float4*>(crow + q*4);
    float4 av = *reinterpret_cast<const float4*>(ati + hf*32 + q*4);
    float4 aw = *reinterpret_cast<const float4*>(atj + hf*32 + q*4);
    si += c4.x*av.x + c4.y*av.y + c4.z*av.z + c4.w*av.w;
    sj += c4.x*aw.x + c4.y*aw.y + c4.z*aw.z + c4.w*aw.w;
    cv.h2[q*2]   = __floats2half2_rn(c4.x, c4.y);
    cv.h2[q*2+1] = __floats2half2_rn(c4.z, c4.w);
  }
  uint4* ghp = reinterpret_cast<uint4*>(d_gh2);
  int grow = blk*128 + row;
  #pragma unroll
  for(int q=0; q<4; q++) ghp[(size_t)grow*8 + hf*4 + q] = cv.u4[q];
  s_si[row][hf] = si; s_sj[row][hf] = sj;
  __syncthreads();
  if(t < 128){
    int gr = blk*128 + t;
    d_si[gr] = s_si[t][0] + s_si[t][1];   // eai added in attn
    d_sj[gr] = s_sj[t][0] + s_sj[t][1];
  }
}

__global__ void __launch_bounds__(256,3) k_work(const float* __restrict__ x,
                      const float* __restrict__ W,
                      const float* __restrict__ ati, const float* __restrict__ atj,
                      const float* __restrict__ embed,
                      const float* __restrict__ aemi, const float* __restrict__ aemj){
  extern __shared__ char gsm[];
  if(blockIdx.x < PRE_BLOCKS) pre_body(gsm, embed, aemi, aemj);
  else                        gemm_body(gsm, blockIdx.x - PRE_BLOCKS, x, W, ati, atj);
}

// ==== merged attn + tail: 256 persistent blocks x 512 threads ====
// dyn smem floats: g(16384) + sj(512) + si(256) = 17152 -> 68608 B
// g region is reused as the agg cache (64KB = 256 rows fp32) after attn.
#define AT_SMEM_FLOATS (16384 + 512 + 256)
#define AT_SMEM_BYTES  (AT_SMEM_FLOATS*4)

__device__ __forceinline__ void gridBarrier256(){
  __threadfence();
  __syncthreads();
  if(threadIdx.x == 0){
    unsigned old = atomicAdd(&g_bar, 1u);
    unsigned target = (old/(unsigned)GB_N + 1u) * (unsigned)GB_N;
    while(((*(volatile unsigned*)&g_bar) - target) & 0x80000000u) __nanosleep(16);
  }
  __syncthreads();
}

__device__ __forceinline__ void reduceScale256(const float* __restrict__ ps,
                                               const float* __restrict__ pq,
                                               const float* __restrict__ gamma,
                                               const float* __restrict__ beta,
                                               float* __restrict__ scale,
                                               float* __restrict__ shift){
  __shared__ float shS[16], shQ[16];
  int c = blockIdx.x, t = threadIdx.x, w = t>>5;
  float s = (t < GB_N) ? ps[c*GB_N + t] : 0.f;
  float q = (t < GB_N) ? pq[c*GB_N + t] : 0.f;
  s = warpSum(s); q = warpSum(q);
  if((t&31)==0){ shS[w]=s; shQ[w]=q; }
  __syncthreads();
  if(t==0){
    float S=0.f, Q=0.f;
    #pragma unroll
    for(int ww=0; ww<16; ww++){ S+=shS[ww]; Q+=shQ[ww]; }
    float mu  = S * (1.0f/(float)BN);
    float var = Q * (1.0f/(float)BN) - mu*mu;
    float sc  = gamma[c] * rsqrtf(var + 1e-5f);
    scale[c] = sc;
    shift[c] = beta[c] - mu*sc;
  }
  __syncthreads();
}

__global__ void __launch_bounds__(512,2) k_attn_tail(
                      const float* __restrict__ gnn_bias,
                      const float* __restrict__ embed,
                      const float* __restrict__ g1, const float* __restrict__ b1,
                      const float* __restrict__ g2, const float* __restrict__ b2,
                      const float* __restrict__ outW, const float* __restrict__ outB,
                      float* __restrict__ out){
  extern __shared__ float sm[];
  __half2* gh_sm = reinterpret_cast<__half2*>(sm);   // [src*32 + lane]
  float* sj_sm = sm + 16384;   // 512
  float* si_sm = sm + 16896;   // 256
  __shared__ float shp[2048], shq2[2048];            // static: reduce scratch

  int t = threadIdx.x, lane = t & 31, w = t >> 5;
  int b        = blockIdx.x >> 1;
  int row_base = (blockIdx.x & 1) * 256;

  const uint4* s4 = reinterpret_cast<const uint4*>(d_gh2 + (size_t)b*16384);
  uint4* dst4 = reinterpret_cast<uint4*>(sm);
  #pragma unroll
  for(int q=0; q<8; q++) dst4[q*512+t] = s4[q*512+t];
  sj_sm[t] = d_sj[b*512+t] + d_eaj[t];
  if(t < 256) si_sm[t] = d_si[b*512 + row_base + t] + d_eai[row_base + t];
  __syncthreads();

  float2 bi2 = reinterpret_cast<const float2*>(gnn_bias)[lane];
  float2 ps = make_float2(0.f,0.f), pq = make_float2(0.f,0.f);

  // ---- attn: 2 rows per iteration (tile0 + tile1) for ILP ----
  for(int it=0; it<8; it++){
    int lr0 = w*8 + it;             // local row in [0,128)
    int lr1 = 128 + w*8 + it;       // local row in [128,256)
    int i0  = row_base + lr0;
    int i1  = row_base + lr1;
    int src0 = (lane < Kk) ? d_topk[i0*Kk + lane] : i0;
    int src1 = (lane < Kk) ? d_topk[i1*Kk + lane] : i1;
    float z0, z1;
    if(lane <= Kk){
      z0 = si_sm[lr0] + sj_sm[src0];
      z0 = (z0 > 0.f) ? z0 : 0.2f*z0;
      if(lane < Kk && src0 == i0) z0 = -INFINITY;
      z1 = si_sm[lr1] + sj_sm[src1];
      z1 = (z1 > 0.f) ? z1 : 0.2f*z1;
      if(lane < Kk && src1 == i1) z1 = -INFINITY;
    } else { z0 = -INFINITY; z1 = -INFINITY; }
    float e0 = (lane <= Kk) ? __expf(z0) : 0.f;
    float e1 = (lane <= Kk) ? __expf(z1) : 0.f;
    float s0 = e0, s1 = e1;
    #pragma unroll
    for(int o=16;o;o>>=1){
      s0 += __shfl_xor_sync(0xffffffffu, s0, o);
      s1 += __shfl_xor_sync(0xffffffffu, s1, o);
    }
    float a0 = __fdividef(e0, s0);
    float a1 = __fdividef(e1, s1);
    unsigned p0 = (__float_as_uint(a0) & 0xFFFFFE00u) | (unsigned)src0;
    unsigned p1 = (__float_as_uint(a1) & 0xFFFFFE00u) | (unsigned)src1;

    float2 acc0 = make_float2(0.f,0.f);
    float2 acc1 = make_float2(0.f,0.f);
    #pragma unroll
    for(int e=0; e<=Kk; e++){
      unsigned k0 = __shfl_sync(0xffffffffu, p0, e);
      unsigned k1 = __shfl_sync(0xffffffffu, p1, e);
      float2 v0 = __half22float2(gh_sm[(int)(k0 & 511u)*32 + lane]);
      float2 v1 = __half22float2(gh_sm[(int)(k1 & 511u)*32 + lane]);
      float w0 = __uint_as_float(k0 & 0xFFFFFE00u);
      float w1 = __uint_as_float(k1 & 0xFFFFFE00u);
      acc0.x += w0*v0.x; acc0.y += w0*v0.y;
      acc1.x += w1*v1.x; acc1.y += w1*v1.y;
    }
    acc0.x += bi2.x; acc0.y += bi2.y;
    acc1.x += bi2.x; acc1.y += bi2.y;
    reinterpret_cast<float2*>(&d_agg[(size_t)(b*512+i0)*64])[lane] = acc0;
    reinterpret_cast<float2*>(&d_agg[(size_t)(b*512+i1)*64])[lane] = acc1;
    ps.x += acc0.x + acc1.x; ps.y += acc0.y + acc1.y;
    pq.x += acc0.x*acc0.x + acc1.x*acc1.x;
    pq.y += acc0.y*acc0.y + acc1.y*acc1.y;
  }

  // BN1 partials (use static scratch; g region stays intact until phase 2 overwrites)
  {
    __syncthreads();
    float* rS = shp;          // 16*64
    float* rQ = shq2;
    rS[w*64 + lane*2]   = ps.x;
    rS[w*64 + lane*2+1] = ps.y;
    rQ[w*64 + lane*2]   = pq.x;
    rQ[w*64 + lane*2+1] = pq.y;
    __syncthreads();
    if(t < 64){
      float S=0.f, Q=0.f;
      #pragma unroll
      for(int ww=0; ww<16; ww++){ S += rS[ww*64+t]; Q += rQ[ww*64+t]; }
      d_ps1[t*GB_N + blockIdx.x] = S;
      d_pq1[t*GB_N + blockIdx.x] = Q;
    }
  }
  gridBarrier256();

  // phase 1: BN1 scale/shift (blocks 0..63)
  if(blockIdx.x < 64)
    reduceScale256(d_ps1, d_pq1, g1, b1, d_scale1, d_shift1);
  gridBarrier256();

  // phase 2: BN2 stats over own 256 rows; cache agg into dead g region (64KB)
  {
    float4* aggc = reinterpret_cast<float4*>(sm);   // 4096 float4
    int d0 = (t & 15) * 4;
    float4 sc1 = *reinterpret_cast<const float4*>(&d_scale1[d0]);
    float4 sh1 = *reinterpret_cast<const float4*>(&d_shift1[d0]);
    float4 psum = make_float4(0.f,0.f,0.f,0.f);
    float4 psq  = make_float4(0.f,0.f,0.f,0.f);
    #pragma unroll
    for(int q=0; q<8; q++){
      int i = blockIdx.x*4096 + q*512 + t;   // (i&15)==(t&15)
      int row  = i >> 4;
      int node = row & (Nn-1);
      float4 a  = reinterpret_cast<const float4*>(d_agg)[i];
      aggc[q*512 + t] = a;
      float4 em = reinterpret_cast<const float4*>(embed)[node*16 + (t&15)];
      float4 r;
      r.x = fmaxf(a.x*sc1.x+sh1.x, 0.f)*em.x;
      r.y = fmaxf(a.y*sc1.y+sh1.y, 0.f)*em.y;
      r.z = fmaxf(a.z*sc1.z+sh1.z, 0.f)*em.z;
      r.w = fmaxf(a.w*sc1.w+sh1.w, 0.f)*em.w;
      psum.x += r.x; psum.y += r.y; psum.z += r.z; psum.w += r.w;
      psq.x += r.x*r.x; psq.y += r.y*r.y; psq.z += r.z*r.z; psq.w += r.w*r.w;
    }
    __syncthreads();
    shp[t*4+0]=psum.x; shp[t*4+1]=psum.y; shp[t*4+2]=psum.z; shp[t*4+3]=psum.w;
    shq2[t*4+0]=psq.x; shq2[t*4+1]=psq.y; shq2[t*4+2]=psq.z; shq2[t*4+3]=psq.w;
    __syncthreads();
    if(t < 64){
      int grp = t >> 2, comp = t & 3;   // channel = grp*4+comp
      float S=0.f, Q=0.f;
      #pragma unroll
      for(int m=0; m<32; m++){
        S += shp [(grp + m*16)*4 + comp];
        Q += shq2[(grp + m*16)*4 + comp];
      }
      d_ps2[t*GB_N + blockIdx.x] = S;
      d_pq2[t*GB_N + blockIdx.x] = Q;
    }
  }
  gridBarrier256();

  // phase 3: BN2 scale/shift
  if(blockIdx.x < 64)
    reduceScale256(d_ps2, d_pq2, g2, b2, d_scale2, d_shift2);
  gridBarrier256();

  // phase 4: out over own 256 rows, agg from smem cache
  {
    const float4* aggc = reinterpret_cast<const float4*>(sm);
    int sub = t & 15;
    float4 s1  = *reinterpret_cast<const float4*>(&d_scale1[sub*4]);
    float4 h1_ = *reinterpret_cast<const float4*>(&d_shift1[sub*4]);
    float4 s2  = *reinterpret_cast<const float4*>(&d_scale2[sub*4]);
    float4 h2_ = *reinterpret_cast<const float4*>(&d_shift2[sub*4]);
    float4 ow  = *reinterpret_cast<const float4*>(&outW[sub*4]);
    float ob = outB[0];
    #pragma unroll
    for(int it=0; it<8; it++){
      int row  = blockIdx.x*256 + it*32 + (t >> 4);
      int node = row & (Nn-1);
      float4 a  = aggc[it*512 + t];       // same layout as phase-2 store
      float4 em = *reinterpret_cast<const float4*>(&embed[node*64 + sub*4]);
      float hx = fmaxf(a.x*s1.x+h1_.x,0.f)*em.x;
      float hy = fmaxf(a.y*s1.y+h1_.y,0.f)*em.y;
      float hz = fmaxf(a.z*s1.z+h1_.z,0.f)*em.z;
      float hw = fmaxf(a.w*s1.w+h1_.w,0.f)*em.w;
      float p = fmaxf(hx*s2.x+h2_.x,0.f)*ow.x + fmaxf(hy*s2.y+h2_.y,0.f)*ow.y
              + fmaxf(hz*s2.z+h2_.z,0.f)*ow.z + fmaxf(hw*s2.w+h2_.w,0.f)*ow.w;
      #pragma unroll
      for(int o=8; o; o>>=1) p += __shfl_xor_sync(0xffffffffu, p, o);
      if(sub==0) out[row] = p + ob;
    }
  }
}

extern "C" void kernel_launch(void* const* d_in, const int* in_sizes, int n_in,
                              void* d_out, int out_size){
  int iData, iEmbed, iW, iAtI, iAtJ, iAemI, iAemJ, iBias, iG1, iB1, iG2, iB2, iOW, iOB;
  if(n_in >= 15 && in_sizes[1] == 2048){
    iData=0; iEmbed=2; iW=3; iAtI=4; iAtJ=5; iAemI=6; iAemJ=7; iBias=8;
    iG1=9; iB1=10; iG2=11; iB2=12; iOW=13; iOB=14;
  } else {
    iData=0; iEmbed=1; iW=2; iAtI=3; iAtJ=4; iAemI=5; iAemJ=6; iBias=7;
    iG1=8; iB1=9; iG2=10; iB2=11; iOW=12; iOB=13;
  }
  const float* data  = (const float*)d_in[iData];
  const float* embed = (const float*)d_in[iEmbed];
  const float* W     = (const float*)d_in[iW];
  const float* atI   = (const float*)d_in[iAtI];
  const float* atJ   = (const float*)d_in[iAtJ];
  const float* aemI  = (const float*)d_in[iAemI];
  const float* aemJ  = (const float*)d_in[iAemJ];
  const float* bias  = (const float*)d_in[iBias];
  const float* g1    = (const float*)d_in[iG1];
  const float* b1    = (const float*)d_in[iB1];
  const float* g2    = (const float*)d_in[iG2];
  const float* b2    = (const float*)d_in[iB2];
  const float* outW  = (const float*)d_in[iOW];
  const float* outB  = (const float*)d_in[iOB];
  float* out = (float*)d_out;

  cudaFuncSetAttribute(k_work, cudaFuncAttributeMaxDynamicSharedMemorySize, WORK_SMEM);
  cudaFuncSetAttribute(k_attn_tail, cudaFuncAttributeMaxDynamicSharedMemorySize, AT_SMEM_BYTES);

  k_work <<<PRE_BLOCKS + BN/128, 256, WORK_SMEM>>>(data, W, atI, atJ, embed, aemI, aemJ);
  k_attn_tail <<<GB_N, 512, AT_SMEM_BYTES>>>(bias, embed, g1, b1, g2, b2, outW, outB, out);
}